// round 15
// baseline (speedup 1.0000x reference)
#include <cuda_runtime.h>
#include <math.h>

#define NN 100000
#define EE 3200000
#define TB 256
#define GN ((NN + TB - 1) / TB)     // 391 node blocks
#define SK 4                        // GEMV split-K factor

// ---------------- scratch ----------------------------------------------------
__device__ float  g_h2[512];
__device__ float  g_deg[NN];        // ZERO invariant at call entry (load + out tail)
__device__ float4 g_acc4[NN];       // GEMV split-K accumulator; ZERO invariant
__device__ float  g_dinv[NN];
__device__ float2 g_ms1[NN];        // m1 * dinv
__device__ float2 g_agg1[NN];       // conv1 accumulator (pre-factored self-loop seed)
__device__ float  g_ms2[NN];
__device__ float  g_agg2[NN];
__device__ int2   g_edge[EE];       // packed (src,dst) — int64 input path only
__device__ int    g_is64;

// phase flags (zero at load; reset by last out block each call)
__device__ volatile unsigned g_f_mlp;
__device__ volatile unsigned g_f_post;
__device__ volatile unsigned g_f_node2;
__device__ volatile unsigned g_f_edge2;
__device__ volatile unsigned g_f_out;

__device__ __forceinline__ void block_release(volatile unsigned* f) {
    __syncthreads();
    if (threadIdx.x == 0) { __threadfence(); atomicAdd((unsigned*)f, 1u); }
}
__device__ __forceinline__ void block_wait(volatile unsigned* f, unsigned tgt) {
    if (threadIdx.x == 0) { while (*f < tgt) __nanosleep(200); }
    __syncthreads();
}

// ---------------- k_big: MLP | split-K sparse GEMV | edge-prep ---------------
// bids [0,4)            MLP front (releases g_f_mlp)
// bids [4,4+SK*GN)      split-K GEMV partials -> red.v4 into g_acc4
// bids [4+SK*GN,...)    edge prep: detect + degrees (+pack iff int64)
__global__ void k_big(const float*  __restrict__ x,
                      const float*  __restrict__ W1,
                      const float*  __restrict__ b1,
                      const float*  __restrict__ W2,
                      const float*  __restrict__ b2,
                      const float4* __restrict__ W3,
                      const float4* __restrict__ b3,
                      const void*   __restrict__ ei, int E) {
    int b = blockIdx.x;
    int t = threadIdx.x;

    if (b < 4) {
        // ---- MLP: h2 = relu(relu(x@W1+b1)@W2+b2), 128 outputs per block ----
        __shared__ float sx[128];
        __shared__ float sh1[256];
        __shared__ float red[256];
        if (t < 128) sx[t] = x[t];
        __syncthreads();

        float acc = 0.f;
        #pragma unroll 8
        for (int k = 0; k < 128; k++) acc = fmaf(sx[k], W1[k * 256 + t], acc);
        sh1[t] = fmaxf(acc + b1[t], 0.f);
        __syncthreads();

        int j = b * 128 + (t & 127);
        int slice = t >> 7;
        float a2 = 0.f;
        int k0 = slice * 128;
        #pragma unroll 8
        for (int k = k0; k < k0 + 128; k++) a2 = fmaf(sh1[k], W2[k * 512 + j], a2);
        red[t] = a2;
        __syncthreads();
        if (slice == 0) g_h2[j] = fmaxf(red[t] + red[t + 128] + b2[j], 0.f);
        block_release(&g_f_mlp);
        return;
    }

    if (b < 4 + SK * GN) {
        // ---- split-K sparse GEMV: partial over 1/SK of nonzero h2 rows ----
        __shared__ float sv[512];
        __shared__ int   si[512];
        __shared__ int   scount;
        int gb    = b - 4;
        int slice = gb / GN;          // 0..SK-1
        int chunk = gb % GN;
        int n = chunk * TB + t;

        float4 acc = make_float4(0.f, 0.f, 0.f, 0.f);
        if (slice == 0 && n < NN) acc = __ldcs(b3 + n);  // prefetch before wait

        if (t == 0) scount = 0;
        block_wait(&g_f_mlp, 4);

        #pragma unroll
        for (int i = t; i < 512; i += TB) {
            float v = g_h2[i];
            if (v != 0.f) {
                int p = atomicAdd(&scount, 1);
                sv[p] = v;
                si[p] = i * 100000;              // pre-scaled row offset (float4 units)
            }
        }
        __syncthreads();
        int cnt = scount;
        int k0 = (slice * cnt) / SK;
        int k1 = ((slice + 1) * cnt) / SK;

        if (n >= NN) return;
        const float4* Wp = W3 + n;
        int k = k0;
        for (; k + 4 <= k1; k += 4) {
            float4 wa = __ldcs(Wp + si[k]);
            float4 wb = __ldcs(Wp + si[k + 1]);
            float4 wc = __ldcs(Wp + si[k + 2]);
            float4 wd = __ldcs(Wp + si[k + 3]);
            float ha = sv[k], hb = sv[k + 1], hc = sv[k + 2], hd = sv[k + 3];
            acc.x = fmaf(ha, wa.x, acc.x); acc.y = fmaf(ha, wa.y, acc.y);
            acc.z = fmaf(ha, wa.z, acc.z); acc.w = fmaf(ha, wa.w, acc.w);
            acc.x = fmaf(hb, wb.x, acc.x); acc.y = fmaf(hb, wb.y, acc.y);
            acc.z = fmaf(hb, wb.z, acc.z); acc.w = fmaf(hb, wb.w, acc.w);
            acc.x = fmaf(hc, wc.x, acc.x); acc.y = fmaf(hc, wc.y, acc.y);
            acc.z = fmaf(hc, wc.z, acc.z); acc.w = fmaf(hc, wc.w, acc.w);
            acc.x = fmaf(hd, wd.x, acc.x); acc.y = fmaf(hd, wd.y, acc.y);
            acc.z = fmaf(hd, wd.z, acc.z); acc.w = fmaf(hd, wd.w, acc.w);
        }
        for (; k < k1; k++) {
            float4 w = __ldcs(Wp + si[k]);
            float  h = sv[k];
            acc.x = fmaf(h, w.x, acc.x); acc.y = fmaf(h, w.y, acc.y);
            acc.z = fmaf(h, w.z, acc.z); acc.w = fmaf(h, w.w, acc.w);
        }
        asm volatile("red.global.add.v4.f32 [%0], {%1, %2, %3, %4};"
                     :: "l"(&g_acc4[n]),
                        "f"(acc.x), "f"(acc.y), "f"(acc.z), "f"(acc.w) : "memory");
        return;
    }

    // ---- edge prep: dtype detect, degrees, pack iff int64 ----
    __shared__ int s_is64;
    if (t < 32) {
        long long v = __ldcs(((const long long*)ei) + t);
        unsigned bad = __ballot_sync(0xFFFFFFFF, v < 0 || v >= NN);
        if (t == 0) { s_is64 = (bad == 0) ? 1 : 0; }
    }
    __syncthreads();
    int is64 = s_is64;
    if (b == 4 + SK * GN && t == 0) g_is64 = is64;

    int e = ((b - 4 - SK * GN) * TB + t) * 4;
    if (e >= E) return;
    if (is64) {
        if (e + 3 < E) {
            const long long* p = (const long long*)ei;
            longlong2 sa = __ldcs((const longlong2*)(p + e));
            longlong2 sb = __ldcs((const longlong2*)(p + e + 2));
            longlong2 da = __ldcs((const longlong2*)(p + E + e));
            longlong2 db = __ldcs((const longlong2*)(p + E + e + 2));
            int s0 = (int)sa.x, s1 = (int)sa.y, s2 = (int)sb.x, s3 = (int)sb.y;
            int d0 = (int)da.x, d1 = (int)da.y, d2 = (int)db.x, d3 = (int)db.y;
            __stcs((int4*)&g_edge[e],     make_int4(s0, d0, s1, d1));
            __stcs((int4*)&g_edge[e + 2], make_int4(s2, d2, s3, d3));
            atomicAdd(&g_deg[d0], 1.0f);
            atomicAdd(&g_deg[d1], 1.0f);
            atomicAdd(&g_deg[d2], 1.0f);
            atomicAdd(&g_deg[d3], 1.0f);
        } else {
            const long long* p = (const long long*)ei;
            for (int i = e; i < E; i++) {
                int s = (int)p[i], d = (int)p[E + i];
                g_edge[i] = make_int2(s, d);
                atomicAdd(&g_deg[d], 1.0f);
            }
        }
    } else {
        // int32: no packing — edge kernels read ei directly
        const int* dst = (const int*)ei + E;
        if (e + 3 < E) {
            int4 dv = __ldcs((const int4*)(dst + e));
            atomicAdd(&g_deg[dv.x], 1.0f);
            atomicAdd(&g_deg[dv.y], 1.0f);
            atomicAdd(&g_deg[dv.z], 1.0f);
            atomicAdd(&g_deg[dv.w], 1.0f);
        } else {
            for (int i = e; i < E; i++) atomicAdd(&g_deg[dst[i]], 1.0f);
        }
    }
}

// ---------------- k_e1: post (bids [0,GN)) + conv1 edge scatter --------------
// Stream order guarantees all GEMV partials and degrees are final here.
__global__ void k_e1(const float* __restrict__ Wg1,
                     const void* __restrict__ ei, int E) {
    int b = blockIdx.x;
    int t = threadIdx.x;

    if (b < GN) {
        int n = b * TB + t;
        if (n < NN) {
            float4 a = g_acc4[n];
            float h0 = fmaxf(a.x, 0.f);
            float h1 = fmaxf(a.y, 0.f);
            float h2 = fmaxf(a.z, 0.f);
            float h3 = fmaxf(a.w, 0.f);
            float m0 = h0 * Wg1[0] + h1 * Wg1[2] + h2 * Wg1[4] + h3 * Wg1[6];
            float m1 = h0 * Wg1[1] + h1 * Wg1[3] + h2 * Wg1[5] + h3 * Wg1[7];
            float di = rsqrtf(g_deg[n] + 1.0f);  // +1 self-loop
            g_dinv[n] = di;
            float2 v = make_float2(m0 * di, m1 * di);
            g_ms1[n]  = v;
            g_agg1[n] = v;                       // pre-factored self-loop seed
            g_acc4[n] = make_float4(0.f, 0.f, 0.f, 0.f);  // restore invariant
        }
        block_release(&g_f_post);
        return;
    }
    block_wait(&g_f_post, GN);

    int e = ((b - GN) * TB + t) * 4;
    if (e >= E) return;
    if (!g_is64) {
        const int* src = (const int*)ei;
        const int* dst = src + E;
        if (e + 3 < E) {
            int4 sv = __ldcs((const int4*)(src + e));
            int4 dv = __ldcs((const int4*)(dst + e));
            float2 a = g_ms1[sv.x];
            float2 b2 = g_ms1[sv.y];
            float2 c = g_ms1[sv.z];
            float2 d = g_ms1[sv.w];
            asm volatile("red.global.add.v2.f32 [%0], {%1, %2};"
                         :: "l"(&g_agg1[dv.x]), "f"(a.x), "f"(a.y) : "memory");
            asm volatile("red.global.add.v2.f32 [%0], {%1, %2};"
                         :: "l"(&g_agg1[dv.y]), "f"(b2.x), "f"(b2.y) : "memory");
            asm volatile("red.global.add.v2.f32 [%0], {%1, %2};"
                         :: "l"(&g_agg1[dv.z]), "f"(c.x), "f"(c.y) : "memory");
            asm volatile("red.global.add.v2.f32 [%0], {%1, %2};"
                         :: "l"(&g_agg1[dv.w]), "f"(d.x), "f"(d.y) : "memory");
        } else {
            for (int i = e; i < E; i++) {
                float2 a = g_ms1[src[i]];
                asm volatile("red.global.add.v2.f32 [%0], {%1, %2};"
                             :: "l"(&g_agg1[dst[i]]), "f"(a.x), "f"(a.y) : "memory");
            }
        }
    } else {
        if (e + 3 < E) {
            int4 ea = __ldcs((const int4*)&g_edge[e]);
            int4 eb = __ldcs((const int4*)&g_edge[e + 2]);
            float2 a = g_ms1[ea.x];
            float2 c = g_ms1[ea.z];
            float2 d = g_ms1[eb.x];
            float2 f = g_ms1[eb.z];
            asm volatile("red.global.add.v2.f32 [%0], {%1, %2};"
                         :: "l"(&g_agg1[ea.y]), "f"(a.x), "f"(a.y) : "memory");
            asm volatile("red.global.add.v2.f32 [%0], {%1, %2};"
                         :: "l"(&g_agg1[ea.w]), "f"(c.x), "f"(c.y) : "memory");
            asm volatile("red.global.add.v2.f32 [%0], {%1, %2};"
                         :: "l"(&g_agg1[eb.y]), "f"(d.x), "f"(d.y) : "memory");
            asm volatile("red.global.add.v2.f32 [%0], {%1, %2};"
                         :: "l"(&g_agg1[eb.w]), "f"(f.x), "f"(f.y) : "memory");
        } else {
            for (int i = e; i < E; i++) {
                int2 ed = g_edge[i];
                float2 a = g_ms1[ed.x];
                asm volatile("red.global.add.v2.f32 [%0], {%1, %2};"
                             :: "l"(&g_agg1[ed.y]), "f"(a.x), "f"(a.y) : "memory");
            }
        }
    }
}

// ---------------- k_e2: node2 | conv2 scatter | sigmoid out ------------------
__global__ void k_e2(const float* __restrict__ bg1,
                     const float* __restrict__ Wg2,
                     const float* __restrict__ bg2,
                     float* __restrict__ out,
                     const void* __restrict__ ei, int E, int gE) {
    int b = blockIdx.x;
    int t = threadIdx.x;

    if (b < GN) {
        int n = b * TB + t;
        if (n < NN) {
            float  di = g_dinv[n];
            float2 a  = g_agg1[n];
            float z0 = fmaxf(a.x * di + bg1[0], 0.f);
            float z1 = fmaxf(a.y * di + bg1[1], 0.f);
            float m2 = z0 * Wg2[0] + z1 * Wg2[1];
            g_ms2[n]  = m2 * di;
            g_agg2[n] = m2 * di;                 // pre-factored self-loop seed
        }
        block_release(&g_f_node2);
        return;
    }

    if (b < GN + gE) {
        block_wait(&g_f_node2, GN);
        int e = ((b - GN) * TB + t) * 4;
        if (e < E) {
            if (!g_is64) {
                const int* src = (const int*)ei;
                const int* dst = src + E;
                if (e + 3 < E) {
                    int4 sv = __ldcs((const int4*)(src + e));
                    int4 dv = __ldcs((const int4*)(dst + e));
                    atomicAdd(&g_agg2[dv.x], g_ms2[sv.x]);
                    atomicAdd(&g_agg2[dv.y], g_ms2[sv.y]);
                    atomicAdd(&g_agg2[dv.z], g_ms2[sv.z]);
                    atomicAdd(&g_agg2[dv.w], g_ms2[sv.w]);
                } else {
                    for (int i = e; i < E; i++)
                        atomicAdd(&g_agg2[dst[i]], g_ms2[src[i]]);
                }
            } else {
                if (e + 3 < E) {
                    int4 ea = __ldcs((const int4*)&g_edge[e]);
                    int4 eb = __ldcs((const int4*)&g_edge[e + 2]);
                    atomicAdd(&g_agg2[ea.y], g_ms2[ea.x]);
                    atomicAdd(&g_agg2[ea.w], g_ms2[ea.z]);
                    atomicAdd(&g_agg2[eb.y], g_ms2[eb.x]);
                    atomicAdd(&g_agg2[eb.w], g_ms2[eb.z]);
                } else {
                    for (int i = e; i < E; i++) {
                        int2 ed = g_edge[i];
                        atomicAdd(&g_agg2[ed.y], g_ms2[ed.x]);
                    }
                }
            }
        }
        block_release(&g_f_edge2);
        return;
    }

    // ---- out phase ----
    block_wait(&g_f_edge2, (unsigned)gE);
    int n = (b - GN - gE) * TB + t;
    if (n < NN) {
        float v = g_agg2[n] * g_dinv[n] + bg2[0];
        out[n] = 1.0f / (1.0f + expf(-v));
        g_deg[n] = 0.0f;                         // restore invariant
    }
    __syncthreads();
    if (t == 0) {
        unsigned done = atomicAdd((unsigned*)&g_f_out, 1u);
        if (done == GN - 1) {                    // last out block: reset flags
            g_f_mlp = 0; g_f_post = 0; g_f_node2 = 0; g_f_edge2 = 0; g_f_out = 0;
        }
    }
}

// ---------------- launch ----------------------------------------------------
extern "C" void kernel_launch(void* const* d_in, const int* in_sizes, int n_in,
                              void* d_out, int out_size) {
    const float* x   = (const float*)d_in[0];
    const void*  ei  = d_in[1];
    const float* W1  = (const float*)d_in[2];
    const float* b1  = (const float*)d_in[3];
    const float* W2  = (const float*)d_in[4];
    const float* b2  = (const float*)d_in[5];
    const float* W3  = (const float*)d_in[6];
    const float* b3  = (const float*)d_in[7];
    const float* Wg1 = (const float*)d_in[8];
    const float* bg1 = (const float*)d_in[9];
    const float* Wg2 = (const float*)d_in[10];
    const float* bg2 = (const float*)d_in[11];
    float* out = (float*)d_out;

    int E = in_sizes[1] / 2;
    if (E > EE) E = EE;

    int gE4 = ((E + 3) / 4 + TB - 1) / TB;       // 3125 for E=3.2M

    k_big<<<4 + SK * GN + gE4, TB>>>(x, W1, b1, W2, b2,
                                     (const float4*)W3, (const float4*)b3,
                                     ei, E);
    k_e1 <<<GN + gE4, TB>>>(Wg1, ei, E);
    k_e2 <<<GN + gE4 + GN, TB>>>(bg1, Wg2, bg2, out, ei, E, gE4);
}

// round 16
// speedup vs baseline: 1.0336x; 1.0336x over previous
#include <cuda_runtime.h>
#include <math.h>

#define NN 100000
#define EE 3200000
#define TB 256
#define GN ((NN + TB - 1) / TB)     // 391 node blocks

// ---------------- scratch ----------------------------------------------------
__device__ float  g_h2[512];
__device__ float  g_deg[NN];        // ZERO invariant at call entry (load + out tail)
__device__ float  g_dinv[NN];
__device__ float2 g_ms1[NN];        // m1 * dinv (written final by GEMV post step)
__device__ float2 g_agg1[NN];       // conv1 accumulator (pre-factored self-loop seed)
__device__ float  g_ms2[NN];
__device__ float  g_agg2[NN];
__device__ int2   g_edge[EE];       // packed (src,dst) — int64 input path only
__device__ int    g_is64;

// phase flags (zero at load; reset by last out block each call)
__device__ volatile unsigned g_f_mlp;
__device__ volatile unsigned g_f_prep;
__device__ volatile unsigned g_f_node2;
__device__ volatile unsigned g_f_edge2;
__device__ volatile unsigned g_f_out;

__device__ __forceinline__ void block_release(volatile unsigned* f) {
    __syncthreads();
    if (threadIdx.x == 0) { __threadfence(); atomicAdd((unsigned*)f, 1u); }
}
__device__ __forceinline__ void block_wait(volatile unsigned* f, unsigned tgt) {
    if (threadIdx.x == 0) { while (*f < tgt) __nanosleep(200); }
    __syncthreads();
}

// ---------------- k_big: MLP | sparse GEMV + post | edge-prep ----------------
// bids [0,4)        MLP front (releases g_f_mlp)
// bids [4,4+GN)     sparse GEMV (waits g_f_mlp), then post (waits g_f_prep)
// bids [4+GN,...)   edge prep: detect + degrees (+pack iff int64); release g_f_prep
__global__ void k_big(const float*  __restrict__ x,
                      const float*  __restrict__ W1,
                      const float*  __restrict__ b1,
                      const float*  __restrict__ W2,
                      const float*  __restrict__ b2,
                      const float4* __restrict__ W3,
                      const float4* __restrict__ b3,
                      const float*  __restrict__ Wg1,
                      const void*   __restrict__ ei, int E, int nPrep) {
    int b = blockIdx.x;
    int t = threadIdx.x;

    if (b < 4) {
        // ---- MLP: h2 = relu(relu(x@W1+b1)@W2+b2), 128 outputs per block ----
        __shared__ float sx[128];
        __shared__ float sh1[256];
        __shared__ float red[256];
        if (t < 128) sx[t] = x[t];
        __syncthreads();

        float acc = 0.f;
        #pragma unroll 8
        for (int k = 0; k < 128; k++) acc = fmaf(sx[k], W1[k * 256 + t], acc);
        sh1[t] = fmaxf(acc + b1[t], 0.f);
        __syncthreads();

        int j = b * 128 + (t & 127);
        int slice = t >> 7;
        float a2 = 0.f;
        int k0 = slice * 128;
        #pragma unroll 8
        for (int k = k0; k < k0 + 128; k++) a2 = fmaf(sh1[k], W2[k * 512 + j], a2);
        red[t] = a2;
        __syncthreads();
        if (slice == 0) g_h2[j] = fmaxf(red[t] + red[t + 128] + b2[j], 0.f);
        block_release(&g_f_mlp);
        return;
    }

    if (b < 4 + GN) {
        // ---- sparse GEMV over nonzero h2 rows (~half of 512), unroll 8 ----
        __shared__ float sv[512];
        __shared__ int   si[512];
        __shared__ int   scount;
        __shared__ float swg[8];
        int n = (b - 4) * TB + t;

        float4 acc = make_float4(0.f, 0.f, 0.f, 0.f);
        if (n < NN) acc = __ldcs(b3 + n);        // prefetch before wait

        if (t == 0) scount = 0;
        if (t < 8) swg[t] = Wg1[t];
        block_wait(&g_f_mlp, 4);

        #pragma unroll
        for (int i = t; i < 512; i += TB) {
            float v = g_h2[i];
            if (v != 0.f) {
                int p = atomicAdd(&scount, 1);
                sv[p] = v;
                si[p] = i * 100000;              // pre-scaled row offset (float4 units)
            }
        }
        __syncthreads();
        int cnt = scount;

        float m0 = 0.f, m1 = 0.f;
        if (n < NN) {
            const float4* Wp = W3 + n;
            int k = 0;
            for (; k + 8 <= cnt; k += 8) {
                // stage 8 indices, then 8 loads in flight, then 32 FMAs
                int i0 = si[k],     i1 = si[k + 1], i2 = si[k + 2], i3 = si[k + 3];
                int i4 = si[k + 4], i5 = si[k + 5], i6 = si[k + 6], i7 = si[k + 7];
                float4 wa = __ldcs(Wp + i0);
                float4 wb = __ldcs(Wp + i1);
                float4 wc = __ldcs(Wp + i2);
                float4 wd = __ldcs(Wp + i3);
                float4 we = __ldcs(Wp + i4);
                float4 wf = __ldcs(Wp + i5);
                float4 wg = __ldcs(Wp + i6);
                float4 wh = __ldcs(Wp + i7);
                float ha = sv[k],     hb = sv[k + 1], hc = sv[k + 2], hd = sv[k + 3];
                float he = sv[k + 4], hf = sv[k + 5], hg = sv[k + 6], hh = sv[k + 7];
                acc.x = fmaf(ha, wa.x, acc.x); acc.y = fmaf(ha, wa.y, acc.y);
                acc.z = fmaf(ha, wa.z, acc.z); acc.w = fmaf(ha, wa.w, acc.w);
                acc.x = fmaf(hb, wb.x, acc.x); acc.y = fmaf(hb, wb.y, acc.y);
                acc.z = fmaf(hb, wb.z, acc.z); acc.w = fmaf(hb, wb.w, acc.w);
                acc.x = fmaf(hc, wc.x, acc.x); acc.y = fmaf(hc, wc.y, acc.y);
                acc.z = fmaf(hc, wc.z, acc.z); acc.w = fmaf(hc, wc.w, acc.w);
                acc.x = fmaf(hd, wd.x, acc.x); acc.y = fmaf(hd, wd.y, acc.y);
                acc.z = fmaf(hd, wd.z, acc.z); acc.w = fmaf(hd, wd.w, acc.w);
                acc.x = fmaf(he, we.x, acc.x); acc.y = fmaf(he, we.y, acc.y);
                acc.z = fmaf(he, we.z, acc.z); acc.w = fmaf(he, we.w, acc.w);
                acc.x = fmaf(hf, wf.x, acc.x); acc.y = fmaf(hf, wf.y, acc.y);
                acc.z = fmaf(hf, wf.z, acc.z); acc.w = fmaf(hf, wf.w, acc.w);
                acc.x = fmaf(hg, wg.x, acc.x); acc.y = fmaf(hg, wg.y, acc.y);
                acc.z = fmaf(hg, wg.z, acc.z); acc.w = fmaf(hg, wg.w, acc.w);
                acc.x = fmaf(hh, wh.x, acc.x); acc.y = fmaf(hh, wh.y, acc.y);
                acc.z = fmaf(hh, wh.z, acc.z); acc.w = fmaf(hh, wh.w, acc.w);
            }
            for (; k < cnt; k++) {
                float4 w = __ldcs(Wp + si[k]);
                float  h = sv[k];
                acc.x = fmaf(h, w.x, acc.x); acc.y = fmaf(h, w.y, acc.y);
                acc.z = fmaf(h, w.z, acc.z); acc.w = fmaf(h, w.w, acc.w);
            }
            float h0 = fmaxf(acc.x, 0.f);
            float h1 = fmaxf(acc.y, 0.f);
            float h2 = fmaxf(acc.z, 0.f);
            float h3 = fmaxf(acc.w, 0.f);
            m0 = h0 * swg[0] + h1 * swg[2] + h2 * swg[4] + h3 * swg[6];
            m1 = h0 * swg[1] + h1 * swg[3] + h2 * swg[5] + h3 * swg[7];
        }

        // ---- post: needs final degrees; prep finishes long before GEMV ----
        block_wait(&g_f_prep, (unsigned)nPrep);
        if (n < NN) {
            float di = rsqrtf(g_deg[n] + 1.0f);  // +1 self-loop
            g_dinv[n] = di;
            float2 v = make_float2(m0 * di, m1 * di);
            g_ms1[n]  = v;
            g_agg1[n] = v;                       // pre-factored self-loop seed
        }
        return;
    }

    // ---- edge prep: dtype detect, degrees, pack iff int64 ----
    __shared__ int s_is64;
    if (t < 32) {
        long long v = __ldcs(((const long long*)ei) + t);
        unsigned bad = __ballot_sync(0xFFFFFFFF, v < 0 || v >= NN);
        if (t == 0) { s_is64 = (bad == 0) ? 1 : 0; }
    }
    __syncthreads();
    int is64 = s_is64;
    if (b == 4 + GN && t == 0) g_is64 = is64;

    int e = ((b - 4 - GN) * TB + t) * 4;
    if (e < E) {
        if (is64) {
            if (e + 3 < E) {
                const long long* p = (const long long*)ei;
                longlong2 sa = __ldcs((const longlong2*)(p + e));
                longlong2 sb = __ldcs((const longlong2*)(p + e + 2));
                longlong2 da = __ldcs((const longlong2*)(p + E + e));
                longlong2 db = __ldcs((const longlong2*)(p + E + e + 2));
                int s0 = (int)sa.x, s1 = (int)sa.y, s2 = (int)sb.x, s3 = (int)sb.y;
                int d0 = (int)da.x, d1 = (int)da.y, d2 = (int)db.x, d3 = (int)db.y;
                __stcs((int4*)&g_edge[e],     make_int4(s0, d0, s1, d1));
                __stcs((int4*)&g_edge[e + 2], make_int4(s2, d2, s3, d3));
                atomicAdd(&g_deg[d0], 1.0f);
                atomicAdd(&g_deg[d1], 1.0f);
                atomicAdd(&g_deg[d2], 1.0f);
                atomicAdd(&g_deg[d3], 1.0f);
            } else {
                const long long* p = (const long long*)ei;
                for (int i = e; i < E; i++) {
                    int s = (int)p[i], d = (int)p[E + i];
                    g_edge[i] = make_int2(s, d);
                    atomicAdd(&g_deg[d], 1.0f);
                }
            }
        } else {
            // int32: no packing — edge kernels read ei directly
            const int* dst = (const int*)ei + E;
            if (e + 3 < E) {
                int4 dv = __ldcs((const int4*)(dst + e));
                atomicAdd(&g_deg[dv.x], 1.0f);
                atomicAdd(&g_deg[dv.y], 1.0f);
                atomicAdd(&g_deg[dv.z], 1.0f);
                atomicAdd(&g_deg[dv.w], 1.0f);
            } else {
                for (int i = e; i < E; i++) atomicAdd(&g_deg[dst[i]], 1.0f);
            }
        }
    }
    block_release(&g_f_prep);
}

// ---------------- k_e1: pure conv1 edge scatter ------------------------------
__global__ void k_e1(const void* __restrict__ ei, int E) {
    int e = (blockIdx.x * TB + threadIdx.x) * 4;
    if (e >= E) return;
    if (!g_is64) {
        const int* src = (const int*)ei;
        const int* dst = src + E;
        if (e + 3 < E) {
            int4 sv = __ldcs((const int4*)(src + e));
            int4 dv = __ldcs((const int4*)(dst + e));
            float2 a = g_ms1[sv.x];
            float2 b = g_ms1[sv.y];
            float2 c = g_ms1[sv.z];
            float2 d = g_ms1[sv.w];
            asm volatile("red.global.add.v2.f32 [%0], {%1, %2};"
                         :: "l"(&g_agg1[dv.x]), "f"(a.x), "f"(a.y) : "memory");
            asm volatile("red.global.add.v2.f32 [%0], {%1, %2};"
                         :: "l"(&g_agg1[dv.y]), "f"(b.x), "f"(b.y) : "memory");
            asm volatile("red.global.add.v2.f32 [%0], {%1, %2};"
                         :: "l"(&g_agg1[dv.z]), "f"(c.x), "f"(c.y) : "memory");
            asm volatile("red.global.add.v2.f32 [%0], {%1, %2};"
                         :: "l"(&g_agg1[dv.w]), "f"(d.x), "f"(d.y) : "memory");
        } else {
            for (int i = e; i < E; i++) {
                float2 a = g_ms1[src[i]];
                asm volatile("red.global.add.v2.f32 [%0], {%1, %2};"
                             :: "l"(&g_agg1[dst[i]]), "f"(a.x), "f"(a.y) : "memory");
            }
        }
    } else {
        if (e + 3 < E) {
            int4 ea = __ldcs((const int4*)&g_edge[e]);
            int4 eb = __ldcs((const int4*)&g_edge[e + 2]);
            float2 a = g_ms1[ea.x];
            float2 c = g_ms1[ea.z];
            float2 d = g_ms1[eb.x];
            float2 f = g_ms1[eb.z];
            asm volatile("red.global.add.v2.f32 [%0], {%1, %2};"
                         :: "l"(&g_agg1[ea.y]), "f"(a.x), "f"(a.y) : "memory");
            asm volatile("red.global.add.v2.f32 [%0], {%1, %2};"
                         :: "l"(&g_agg1[ea.w]), "f"(c.x), "f"(c.y) : "memory");
            asm volatile("red.global.add.v2.f32 [%0], {%1, %2};"
                         :: "l"(&g_agg1[eb.y]), "f"(d.x), "f"(d.y) : "memory");
            asm volatile("red.global.add.v2.f32 [%0], {%1, %2};"
                         :: "l"(&g_agg1[eb.w]), "f"(f.x), "f"(f.y) : "memory");
        } else {
            for (int i = e; i < E; i++) {
                int2 ed = g_edge[i];
                float2 a = g_ms1[ed.x];
                asm volatile("red.global.add.v2.f32 [%0], {%1, %2};"
                             :: "l"(&g_agg1[ed.y]), "f"(a.x), "f"(a.y) : "memory");
            }
        }
    }
}

// ---------------- k_e2: node2 | conv2 scatter | sigmoid out ------------------
// bids [0,GN)            node2 (release g_f_node2)
// bids [GN,GN+gE)        conv2 edge scatter (wait node2; release g_f_edge2)
// bids [GN+gE,GN+gE+GN)  out: sigmoid + invariant restore (wait edge2)
__global__ void k_e2(const float* __restrict__ bg1,
                     const float* __restrict__ Wg2,
                     const float* __restrict__ bg2,
                     float* __restrict__ out,
                     const void* __restrict__ ei, int E, int gE) {
    int b = blockIdx.x;
    int t = threadIdx.x;

    if (b < GN) {
        int n = b * TB + t;
        if (n < NN) {
            float  di = g_dinv[n];
            float2 a  = g_agg1[n];
            float z0 = fmaxf(a.x * di + bg1[0], 0.f);
            float z1 = fmaxf(a.y * di + bg1[1], 0.f);
            float m2 = z0 * Wg2[0] + z1 * Wg2[1];
            g_ms2[n]  = m2 * di;
            g_agg2[n] = m2 * di;                 // pre-factored self-loop seed
        }
        block_release(&g_f_node2);
        return;
    }

    if (b < GN + gE) {
        block_wait(&g_f_node2, GN);
        int e = ((b - GN) * TB + t) * 4;
        if (e < E) {
            if (!g_is64) {
                const int* src = (const int*)ei;
                const int* dst = src + E;
                if (e + 3 < E) {
                    int4 sv = __ldcs((const int4*)(src + e));
                    int4 dv = __ldcs((const int4*)(dst + e));
                    atomicAdd(&g_agg2[dv.x], g_ms2[sv.x]);
                    atomicAdd(&g_agg2[dv.y], g_ms2[sv.y]);
                    atomicAdd(&g_agg2[dv.z], g_ms2[sv.z]);
                    atomicAdd(&g_agg2[dv.w], g_ms2[sv.w]);
                } else {
                    for (int i = e; i < E; i++)
                        atomicAdd(&g_agg2[dst[i]], g_ms2[src[i]]);
                }
            } else {
                if (e + 3 < E) {
                    int4 ea = __ldcs((const int4*)&g_edge[e]);
                    int4 eb = __ldcs((const int4*)&g_edge[e + 2]);
                    atomicAdd(&g_agg2[ea.y], g_ms2[ea.x]);
                    atomicAdd(&g_agg2[ea.w], g_ms2[ea.z]);
                    atomicAdd(&g_agg2[eb.y], g_ms2[eb.x]);
                    atomicAdd(&g_agg2[eb.w], g_ms2[eb.z]);
                } else {
                    for (int i = e; i < E; i++) {
                        int2 ed = g_edge[i];
                        atomicAdd(&g_agg2[ed.y], g_ms2[ed.x]);
                    }
                }
            }
        }
        block_release(&g_f_edge2);
        return;
    }

    // ---- out phase ----
    block_wait(&g_f_edge2, (unsigned)gE);
    int n = (b - GN - gE) * TB + t;
    if (n < NN) {
        float v = g_agg2[n] * g_dinv[n] + bg2[0];
        out[n] = 1.0f / (1.0f + expf(-v));
        g_deg[n] = 0.0f;                         // restore invariant
    }
    __syncthreads();
    if (t == 0) {
        unsigned done = atomicAdd((unsigned*)&g_f_out, 1u);
        if (done == GN - 1) {                    // last out block: reset flags
            g_f_mlp = 0; g_f_prep = 0; g_f_node2 = 0; g_f_edge2 = 0; g_f_out = 0;
        }
    }
}

// ---------------- launch ----------------------------------------------------
extern "C" void kernel_launch(void* const* d_in, const int* in_sizes, int n_in,
                              void* d_out, int out_size) {
    const float* x   = (const float*)d_in[0];
    const void*  ei  = d_in[1];
    const float* W1  = (const float*)d_in[2];
    const float* b1  = (const float*)d_in[3];
    const float* W2  = (const float*)d_in[4];
    const float* b2  = (const float*)d_in[5];
    const float* W3  = (const float*)d_in[6];
    const float* b3  = (const float*)d_in[7];
    const float* Wg1 = (const float*)d_in[8];
    const float* bg1 = (const float*)d_in[9];
    const float* Wg2 = (const float*)d_in[10];
    const float* bg2 = (const float*)d_in[11];
    float* out = (float*)d_out;

    int E = in_sizes[1] / 2;
    if (E > EE) E = EE;

    int gE4 = ((E + 3) / 4 + TB - 1) / TB;       // 3125 for E=3.2M

    k_big<<<4 + GN + gE4, TB>>>(x, W1, b1, W2, b2,
                                (const float4*)W3, (const float4*)b3,
                                Wg1, ei, E, gE4);
    k_e1 <<<gE4, TB>>>(ei, E);
    k_e2 <<<GN + gE4 + GN, TB>>>(bg1, Wg2, bg2, out, ei, E, gE4);
}